// round 4
// baseline (speedup 1.0000x reference)
#include <cuda_runtime.h>
#include <cuda_bf16.h>
#include <math.h>

#define NN 100000
#define NE 3200000
#define NG 512
#define F 20   // hidden width

// ---------------- scratch (device globals; no allocation allowed) ------------
__device__ int                g_cnt[NN];          // per-dst degree
__device__ int                g_pos[NN];          // scatter cursor (init = offset)
__device__ int                g_off[NN];          // CSR offsets
__device__ int                g_bsum[128];        // block sums for scan
__device__ unsigned long long g_epack[NE];        // CSR payload: (ew_bits<<32)|src
__device__ float              g_z[NN * F + 32];   // rel-transformed features (+pad)
__device__ float              g_r[NN * F];        // root term + bias
__device__ float              g_h[NN * F];        // current node features

// ---------------- CSR build ---------------------------------------------------
__global__ void __launch_bounds__(256) zero_kernel() {
    int i = blockIdx.x * blockDim.x + threadIdx.x;  // NN/4 rounded
    int4 z = make_int4(0, 0, 0, 0);
    if (i * 4 + 3 < NN) {
        *reinterpret_cast<int4*>(g_cnt + i * 4) = z;
    } else {
        for (int j = i * 4; j < NN; j++) g_cnt[j] = 0;
    }
}

// 8 edges per thread (NE % 8 == 0)
__global__ void __launch_bounds__(256) hist_kernel(const int* __restrict__ dst) {
    int t = blockIdx.x * blockDim.x + threadIdx.x;  // NE/8 threads
    int4 d0 = *reinterpret_cast<const int4*>(dst + t * 8);
    int4 d1 = *reinterpret_cast<const int4*>(dst + t * 8 + 4);
    atomicAdd(&g_cnt[d0.x], 1);
    atomicAdd(&g_cnt[d0.y], 1);
    atomicAdd(&g_cnt[d0.z], 1);
    atomicAdd(&g_cnt[d0.w], 1);
    atomicAdd(&g_cnt[d1.x], 1);
    atomicAdd(&g_cnt[d1.y], 1);
    atomicAdd(&g_cnt[d1.z], 1);
    atomicAdd(&g_cnt[d1.w], 1);
}

// ---- 3-phase scan: 98 blocks x 256 threads x 4 elems ----
#define SCAN_BLOCKS 98
#define SCAN_CHUNK  1024

__device__ __forceinline__ int block_excl_scan_256(int s) {
    int lane = threadIdx.x & 31, w = threadIdx.x >> 5;
    int v = s;
    #pragma unroll
    for (int o = 1; o < 32; o <<= 1) {
        int u = __shfl_up_sync(0xffffffffu, v, o);
        if (lane >= o) v += u;
    }
    __shared__ int wsum[8];
    if (lane == 31) wsum[w] = v;
    __syncthreads();
    if (threadIdx.x == 0) {
        int run = 0;
        #pragma unroll
        for (int i = 0; i < 8; i++) { int tmp = wsum[i]; wsum[i] = run; run += tmp; }
    }
    __syncthreads();
    return (v - s) + wsum[w];
}

__global__ void __launch_bounds__(256) scan1_kernel() {
    int base = blockIdx.x * SCAN_CHUNK + threadIdx.x * 4;
    int s = 0;
    #pragma unroll
    for (int j = 0; j < 4; j++) {
        int i = base + j;
        if (i < NN) s += g_cnt[i];
    }
    int lane = threadIdx.x & 31, w = threadIdx.x >> 5;
    #pragma unroll
    for (int o = 16; o > 0; o >>= 1) s += __shfl_down_sync(0xffffffffu, s, o);
    __shared__ int wsum[8];
    if (lane == 0) wsum[w] = s;
    __syncthreads();
    if (threadIdx.x == 0) {
        int tot = 0;
        #pragma unroll
        for (int i = 0; i < 8; i++) tot += wsum[i];
        g_bsum[blockIdx.x] = tot;
    }
}

__global__ void __launch_bounds__(128) scan2_kernel() {
    __shared__ int sh[SCAN_BLOCKS];
    if (threadIdx.x < SCAN_BLOCKS) sh[threadIdx.x] = g_bsum[threadIdx.x];
    __syncthreads();
    if (threadIdx.x == 0) {
        int run = 0;
        for (int i = 0; i < SCAN_BLOCKS; i++) { int t = sh[i]; sh[i] = run; run += t; }
    }
    __syncthreads();
    if (threadIdx.x < SCAN_BLOCKS) g_bsum[threadIdx.x] = sh[threadIdx.x];
}

__global__ void __launch_bounds__(256) scan3_kernel() {
    int base = blockIdx.x * SCAN_CHUNK + threadIdx.x * 4;
    int c[4]; int s = 0;
    #pragma unroll
    for (int j = 0; j < 4; j++) {
        int i = base + j;
        c[j] = (i < NN) ? g_cnt[i] : 0;
        s += c[j];
    }
    int excl = block_excl_scan_256(s) + g_bsum[blockIdx.x];
    int run = excl;
    #pragma unroll
    for (int j = 0; j < 4; j++) {
        int i = base + j;
        if (i < NN) { g_off[i] = run; g_pos[i] = run; }
        run += c[j];
    }
}

// 8 edges per thread, vector loads, packed 8B payload store
__global__ void __launch_bounds__(256) scatter_kernel(const int* __restrict__ src,
                                                      const int* __restrict__ dst,
                                                      const float* __restrict__ ew) {
    int t = blockIdx.x * blockDim.x + threadIdx.x;  // NE/8 threads
    int4   sv0 = *reinterpret_cast<const int4*>(src + t * 8);
    int4   sv1 = *reinterpret_cast<const int4*>(src + t * 8 + 4);
    int4   dv0 = *reinterpret_cast<const int4*>(dst + t * 8);
    int4   dv1 = *reinterpret_cast<const int4*>(dst + t * 8 + 4);
    float4 wv0 = *reinterpret_cast<const float4*>(ew + t * 8);
    float4 wv1 = *reinterpret_cast<const float4*>(ew + t * 8 + 4);

    int p0 = atomicAdd(&g_pos[dv0.x], 1);
    int p1 = atomicAdd(&g_pos[dv0.y], 1);
    int p2 = atomicAdd(&g_pos[dv0.z], 1);
    int p3 = atomicAdd(&g_pos[dv0.w], 1);
    int p4 = atomicAdd(&g_pos[dv1.x], 1);
    int p5 = atomicAdd(&g_pos[dv1.y], 1);
    int p6 = atomicAdd(&g_pos[dv1.z], 1);
    int p7 = atomicAdd(&g_pos[dv1.w], 1);

    g_epack[p0] = ((unsigned long long)__float_as_uint(wv0.x) << 32) | (unsigned)sv0.x;
    g_epack[p1] = ((unsigned long long)__float_as_uint(wv0.y) << 32) | (unsigned)sv0.y;
    g_epack[p2] = ((unsigned long long)__float_as_uint(wv0.z) << 32) | (unsigned)sv0.z;
    g_epack[p3] = ((unsigned long long)__float_as_uint(wv0.w) << 32) | (unsigned)sv0.w;
    g_epack[p4] = ((unsigned long long)__float_as_uint(wv1.x) << 32) | (unsigned)sv1.x;
    g_epack[p5] = ((unsigned long long)__float_as_uint(wv1.y) << 32) | (unsigned)sv1.y;
    g_epack[p6] = ((unsigned long long)__float_as_uint(wv1.z) << 32) | (unsigned)sv1.z;
    g_epack[p7] = ((unsigned long long)__float_as_uint(wv1.w) << 32) | (unsigned)sv1.w;
}

// ---------------- per-layer transform: z = f@Wrel^T, r = f@Wroot^T + b --------
template <int FIN>
__global__ void __launch_bounds__(256) transform_kernel(const float* __restrict__ xext,
                                                        const float* __restrict__ Wrel,
                                                        const float* __restrict__ brel,
                                                        const float* __restrict__ Wroot,
                                                        int insel) {
    __shared__ float sWrel[F * FIN];
    __shared__ float sWroot[F * FIN];
    __shared__ float sb[F];
    for (int i = threadIdx.x; i < F * FIN; i += blockDim.x) {
        sWrel[i]  = Wrel[i];
        sWroot[i] = Wroot[i];
    }
    if (threadIdx.x < F) sb[threadIdx.x] = brel[threadIdx.x];
    __syncthreads();

    const float* fin = (insel < 0) ? xext : g_h;
    int n = blockIdx.x * blockDim.x + threadIdx.x;
    if (n >= NN) return;

    float f[FIN];
    if (FIN == 20) {
        const float4* p = reinterpret_cast<const float4*>(fin + (long)n * FIN);
        #pragma unroll
        for (int q = 0; q < 5; q++) {
            float4 v = p[q];
            f[q * 4 + 0] = v.x; f[q * 4 + 1] = v.y; f[q * 4 + 2] = v.z; f[q * 4 + 3] = v.w;
        }
    } else {  // FIN == 10
        const float2* p = reinterpret_cast<const float2*>(fin + (long)n * FIN);
        #pragma unroll
        for (int q = 0; q < 5; q++) {
            float2 v = p[q];
            f[q * 2 + 0] = v.x; f[q * 2 + 1] = v.y;
        }
    }

    float z[F], r[F];
    #pragma unroll
    for (int j = 0; j < F; j++) {
        float a = 0.0f, bsum = sb[j];
        #pragma unroll
        for (int k = 0; k < FIN; k++) {
            a    += f[k] * sWrel[j * FIN + k];
            bsum += f[k] * sWroot[j * FIN + k];
        }
        z[j] = a; r[j] = bsum;
    }

    float4* zp = reinterpret_cast<float4*>(g_z + (long)n * F);
    float4* rp = reinterpret_cast<float4*>(g_r + (long)n * F);
    #pragma unroll
    for (int q = 0; q < 5; q++) {
        zp[q] = make_float4(z[q * 4], z[q * 4 + 1], z[q * 4 + 2], z[q * 4 + 3]);
        rp[q] = make_float4(r[q * 4], r[q * 4 + 1], r[q * 4 + 2], r[q * 4 + 3]);
    }
}

// ---------------- gather: warp per node, lane per feature ---------------------
// smem-staged payloads + statically unrolled 8-blocks (dummy edges have w=0,src=0)
__global__ void __launch_bounds__(256) gather_kernel() {
    __shared__ unsigned long long s_pk[8][32];

    int warp = (blockIdx.x * blockDim.x + threadIdx.x) >> 5;
    if (warp >= NN) return;
    int lane = threadIdx.x & 31;
    int w    = (threadIdx.x >> 5) & 7;
    const bool active = lane < F;

    int n   = warp;
    int s0  = g_off[n];
    int cnt = g_cnt[n];

    float acc = 0.0f;
    for (int base = 0; base < cnt; base += 32) {
        int idx = base + lane;
        unsigned long long pk = 0;              // dummy: w=0, src=0 (safe)
        if (idx < cnt) pk = g_epack[s0 + idx];
        s_pk[w][lane] = pk;
        __syncwarp();

        int m = cnt - base;                     // >0
        #pragma unroll
        for (int jj = 0; jj < 32; jj += 8) {
            if (jj >= m) break;                 // warp-uniform
            #pragma unroll
            for (int j = jj; j < jj + 8; j++) {
                unsigned long long v = s_pk[w][j];
                int   s  = (int)(v & 0xffffffffu);
                float wt = __uint_as_float((unsigned)(v >> 32));
                acc += wt * __ldg(g_z + s * F + lane);
            }
        }
        __syncwarp();
    }

    float val = active ? (acc + g_r[(long)n * F + lane]) : 0.0f;
    float ss = val * val;
    #pragma unroll
    for (int o = 16; o > 0; o >>= 1) ss += __shfl_xor_sync(0xffffffffu, ss, o);
    float inv = 1.0f / fmaxf(sqrtf(ss), 1e-12f);
    if (active) g_h[(long)n * F + lane] = fmaxf(val * inv, 0.0f);
}

// ---------------- pooling + final linear (batch sorted -> no atomics) --------
__device__ __forceinline__ int lower_bound_i(const int* __restrict__ a, int n, int key) {
    int lo = 0, hi = n;
    while (lo < hi) {
        int m = (lo + hi) >> 1;
        if (a[m] < key) lo = m + 1; else hi = m;
    }
    return lo;
}

__global__ void __launch_bounds__(256) pool_kernel(const int* __restrict__ batch,
                                                   const float* __restrict__ Wlin,
                                                   const float* __restrict__ blin,
                                                   float* __restrict__ out) {
    const float* emb = g_h;
    int g = blockIdx.x;

    __shared__ int s_lo, s_hi;
    if (threadIdx.x == 0) {
        s_lo = lower_bound_i(batch, NN, g);
        s_hi = lower_bound_i(batch, NN, g + 1);
    }
    __syncthreads();
    int lo = s_lo, hi = s_hi;

    float sm[F], mx[F];
    #pragma unroll
    for (int k = 0; k < F; k++) { sm[k] = 0.0f; mx[k] = 0.0f; }

    for (int i = lo + threadIdx.x; i < hi; i += blockDim.x) {
        const float* r = emb + (long)i * F;
        #pragma unroll
        for (int k = 0; k < F; k++) {
            float v = __ldg(r + k);
            sm[k] += v;
            mx[k] = fmaxf(mx[k], v);
        }
    }

    #pragma unroll
    for (int o = 16; o > 0; o >>= 1) {
        #pragma unroll
        for (int k = 0; k < F; k++) {
            sm[k] += __shfl_down_sync(0xffffffffu, sm[k], o);
            mx[k] = fmaxf(mx[k], __shfl_down_sync(0xffffffffu, mx[k], o));
        }
    }

    __shared__ float ssum[8][F];
    __shared__ float smax[8][F];
    int w = threadIdx.x >> 5, lane = threadIdx.x & 31;
    if (lane == 0) {
        #pragma unroll
        for (int k = 0; k < F; k++) { ssum[w][k] = sm[k]; smax[w][k] = mx[k]; }
    }
    __syncthreads();

    if (threadIdx.x == 0) {
        float fs[F], fm[F];
        #pragma unroll
        for (int k = 0; k < F; k++) { fs[k] = 0.0f; fm[k] = 0.0f; }
        for (int ww = 0; ww < 8; ww++)
            for (int k = 0; k < F; k++) {
                fs[k] += ssum[ww][k];
                fm[k] = fmaxf(fm[k], smax[ww][k]);
            }
        float cnt  = (float)(hi - lo);
        float invc = 1.0f / fmaxf(cnt, 1.0f);
        #pragma unroll
        for (int c = 0; c < 2; c++) {
            float v = blin[c];
            for (int k = 0; k < F; k++) v += fm[k] * Wlin[c * 40 + k];
            for (int k = 0; k < F; k++) v += fs[k] * invc * Wlin[c * 40 + 20 + k];
            out[g * 2 + c] = v;
        }
    }
}

// ---------------- launch ------------------------------------------------------
extern "C" void kernel_launch(void* const* d_in, const int* in_sizes, int n_in,
                              void* d_out, int out_size) {
    (void)in_sizes; (void)n_in; (void)out_size;

    const float* x      = (const float*)d_in[0];
    const int*   ei     = (const int*)  d_in[1];   // [2, NE]: row0=src, row1=dst
    const int*   batch  = (const int*)  d_in[2];
    const float* ew     = (const float*)d_in[3];
    const float* W1_rel = (const float*)d_in[4];
    const float* b1_rel = (const float*)d_in[5];
    const float* W1_root= (const float*)d_in[6];
    const float* W2_rel = (const float*)d_in[7];
    const float* b2_rel = (const float*)d_in[8];
    const float* W2_root= (const float*)d_in[9];
    const float* W3_rel = (const float*)d_in[10];
    const float* b3_rel = (const float*)d_in[11];
    const float* W3_root= (const float*)d_in[12];
    const float* W_lin  = (const float*)d_in[13];
    const float* b_lin  = (const float*)d_in[14];
    float* out = (float*)d_out;

    const int* src = ei;
    const int* dst = ei + NE;

    const int TB = 256;
    const int GB_N  = (NN + TB - 1) / TB;           // 391
    const int GB_Z  = (NN / 4 + TB) / TB;           // zero grid (int4)
    const int GB_E8 = (NE / 8 + TB - 1) / TB;       // 1563
    const int GB_W  = (NN * 32 + TB - 1) / TB;      // 12500

    zero_kernel   <<<GB_Z, TB>>>();
    hist_kernel   <<<GB_E8, TB>>>(dst);
    scan1_kernel  <<<SCAN_BLOCKS, TB>>>();
    scan2_kernel  <<<1, 128>>>();
    scan3_kernel  <<<SCAN_BLOCKS, TB>>>();
    scatter_kernel<<<GB_E8, TB>>>(src, dst, ew);

    transform_kernel<10><<<GB_N, TB>>>(x, W1_rel, b1_rel, W1_root, -1);
    gather_kernel<<<GB_W, TB>>>();
    transform_kernel<20><<<GB_N, TB>>>(x, W2_rel, b2_rel, W2_root, 0);
    gather_kernel<<<GB_W, TB>>>();
    transform_kernel<20><<<GB_N, TB>>>(x, W3_rel, b3_rel, W3_root, 0);
    gather_kernel<<<GB_W, TB>>>();

    pool_kernel<<<NG, 256>>>(batch, W_lin, b_lin, out);
}

// round 5
// speedup vs baseline: 1.2646x; 1.2646x over previous
#include <cuda_runtime.h>
#include <cuda_bf16.h>
#include <math.h>

#define NN 100000
#define NE 3200000
#define NG 512
#define F 20          // hidden width
#define ZP 32         // padded z row (floats) = 128B
#define EPACK_CAP (NE + NN * 8)

// ---------------- scratch (device globals; no allocation allowed) ------------
__device__ int                g_cnt[NN];          // per-dst degree (zeroed by scan3 each call)
__device__ int                g_pos[NN];          // scatter cursor (init = offset)
__device__ int                g_off[NN + 1];      // padded CSR offsets
__device__ int                g_bsum[128];        // block sums for scan
__device__ unsigned long long g_epack[EPACK_CAP]; // CSR payload: (ew_bits<<32)|src
__device__ float              g_z[NN * ZP];       // rel-transformed, 128B-aligned rows
__device__ float              g_r[NN * F];        // root term + bias
__device__ float              g_h[NN * F];        // current node features

// ---------------- CSR build ---------------------------------------------------
// 4 edges per thread (NE % 4 == 0). g_cnt starts zeroed (zero-init, then scan3 re-zeros).
__global__ void __launch_bounds__(256) hist_kernel(const int* __restrict__ dst) {
    int t = blockIdx.x * blockDim.x + threadIdx.x;  // NE/4 threads
    int4 d = *reinterpret_cast<const int4*>(dst + t * 4);
    atomicAdd(&g_cnt[d.x], 1);
    atomicAdd(&g_cnt[d.y], 1);
    atomicAdd(&g_cnt[d.z], 1);
    atomicAdd(&g_cnt[d.w], 1);
}

#define SCAN_BLOCKS 98
#define SCAN_CHUNK  1024   // nodes per block (256 thr x 4)

// phase 1: per-block sums of PADDED counts
__global__ void __launch_bounds__(256) scan1_kernel() {
    int base = blockIdx.x * SCAN_CHUNK + threadIdx.x * 4;
    int s = 0;
    #pragma unroll
    for (int j = 0; j < 4; j++) {
        int i = base + j;
        if (i < NN) s += (g_cnt[i] + 7) & ~7;
    }
    int lane = threadIdx.x & 31, w = threadIdx.x >> 5;
    #pragma unroll
    for (int o = 16; o > 0; o >>= 1) s += __shfl_down_sync(0xffffffffu, s, o);
    __shared__ int wsum[8];
    if (lane == 0) wsum[w] = s;
    __syncthreads();
    if (threadIdx.x == 0) {
        int tot = 0;
        #pragma unroll
        for (int i = 0; i < 8; i++) tot += wsum[i];
        g_bsum[blockIdx.x] = tot;
    }
}

// phase 2+3 fused: each block computes its base from g_bsum, then offsets,
// zeroes pad slots in g_epack, and re-zeroes g_cnt for the next call.
__global__ void __launch_bounds__(256) scan3_kernel() {
    __shared__ int s_base;
    if (threadIdx.x == 0) {
        int run = 0;
        for (int i = 0; i < (int)blockIdx.x; i++) run += g_bsum[i];
        s_base = run;
    }

    int base = blockIdx.x * SCAN_CHUNK + threadIdx.x * 4;
    int c[4], cp[4]; int s = 0;
    #pragma unroll
    for (int j = 0; j < 4; j++) {
        int i = base + j;
        c[j]  = (i < NN) ? g_cnt[i] : 0;
        cp[j] = (c[j] + 7) & ~7;
        s += cp[j];
    }

    // block exclusive scan of s
    int lane = threadIdx.x & 31, w = threadIdx.x >> 5;
    int v = s;
    #pragma unroll
    for (int o = 1; o < 32; o <<= 1) {
        int u = __shfl_up_sync(0xffffffffu, v, o);
        if (lane >= o) v += u;
    }
    __shared__ int wsum[8];
    if (lane == 31) wsum[w] = v;
    __syncthreads();
    if (threadIdx.x == 0) {
        int run = 0;
        #pragma unroll
        for (int i = 0; i < 8; i++) { int tmp = wsum[i]; wsum[i] = run; run += tmp; }
    }
    __syncthreads();
    int excl = (v - s) + wsum[w] + s_base;

    int run = excl;
    #pragma unroll
    for (int j = 0; j < 4; j++) {
        int i = base + j;
        if (i < NN) {
            g_off[i] = run;
            g_pos[i] = run;
            // zero the pad slots [run+c, run+cp)
            for (int p = c[j]; p < cp[j]; p++) g_epack[run + p] = 0ull;
            g_cnt[i] = 0;  // restore invariant for next call
            if (i == NN - 1) g_off[NN] = run + cp[j];
        }
        run += cp[j];
    }
}

// 4 edges per thread, vector loads, packed 8B payload store
__global__ void __launch_bounds__(256) scatter_kernel(const int* __restrict__ src,
                                                      const int* __restrict__ dst,
                                                      const float* __restrict__ ew) {
    int t = blockIdx.x * blockDim.x + threadIdx.x;  // NE/4 threads
    int4   sv = *reinterpret_cast<const int4*>(src + t * 4);
    int4   dv = *reinterpret_cast<const int4*>(dst + t * 4);
    float4 wv = *reinterpret_cast<const float4*>(ew + t * 4);

    int p0 = atomicAdd(&g_pos[dv.x], 1);
    int p1 = atomicAdd(&g_pos[dv.y], 1);
    int p2 = atomicAdd(&g_pos[dv.z], 1);
    int p3 = atomicAdd(&g_pos[dv.w], 1);

    g_epack[p0] = ((unsigned long long)__float_as_uint(wv.x) << 32) | (unsigned)sv.x;
    g_epack[p1] = ((unsigned long long)__float_as_uint(wv.y) << 32) | (unsigned)sv.y;
    g_epack[p2] = ((unsigned long long)__float_as_uint(wv.z) << 32) | (unsigned)sv.z;
    g_epack[p3] = ((unsigned long long)__float_as_uint(wv.w) << 32) | (unsigned)sv.w;
}

// ---------------- per-layer transform: z = f@Wrel^T (padded rows), r = f@Wroot^T + b
template <int FIN>
__global__ void __launch_bounds__(256) transform_kernel(const float* __restrict__ xext,
                                                        const float* __restrict__ Wrel,
                                                        const float* __restrict__ brel,
                                                        const float* __restrict__ Wroot,
                                                        int insel) {
    __shared__ float sWrel[F * FIN];
    __shared__ float sWroot[F * FIN];
    __shared__ float sb[F];
    for (int i = threadIdx.x; i < F * FIN; i += blockDim.x) {
        sWrel[i]  = Wrel[i];
        sWroot[i] = Wroot[i];
    }
    if (threadIdx.x < F) sb[threadIdx.x] = brel[threadIdx.x];
    __syncthreads();

    const float* fin = (insel < 0) ? xext : g_h;
    int n = blockIdx.x * blockDim.x + threadIdx.x;
    if (n >= NN) return;

    float f[FIN];
    if (FIN == 20) {
        const float4* p = reinterpret_cast<const float4*>(fin + (long)n * FIN);
        #pragma unroll
        for (int q = 0; q < 5; q++) {
            float4 v = p[q];
            f[q * 4 + 0] = v.x; f[q * 4 + 1] = v.y; f[q * 4 + 2] = v.z; f[q * 4 + 3] = v.w;
        }
    } else {  // FIN == 10
        const float2* p = reinterpret_cast<const float2*>(fin + (long)n * FIN);
        #pragma unroll
        for (int q = 0; q < 5; q++) {
            float2 v = p[q];
            f[q * 2 + 0] = v.x; f[q * 2 + 1] = v.y;
        }
    }

    float z[F], r[F];
    #pragma unroll
    for (int j = 0; j < F; j++) {
        float a = 0.0f, bsum = sb[j];
        #pragma unroll
        for (int k = 0; k < FIN; k++) {
            a    += f[k] * sWrel[j * FIN + k];
            bsum += f[k] * sWroot[j * FIN + k];
        }
        z[j] = a; r[j] = bsum;
    }

    float4* zp = reinterpret_cast<float4*>(g_z + (long)n * ZP);
    float4* rp = reinterpret_cast<float4*>(g_r + (long)n * F);
    #pragma unroll
    for (int q = 0; q < 5; q++) {
        zp[q] = make_float4(z[q * 4], z[q * 4 + 1], z[q * 4 + 2], z[q * 4 + 3]);
        rp[q] = make_float4(r[q * 4], r[q * 4 + 1], r[q * 4 + 2], r[q * 4 + 3]);
    }
}

// ---------------- gather: warp per node, lane per feature ---------------------
// padded-to-8 segments -> static 8-unrolled shfl blocks, aligned 128B z rows
__global__ void __launch_bounds__(256) gather_kernel() {
    int warp = (blockIdx.x * blockDim.x + threadIdx.x) >> 5;
    if (warp >= NN) return;
    int lane = threadIdx.x & 31;
    const bool active = lane < F;

    int n    = warp;
    int s0   = g_off[n];
    int cntp = g_off[n + 1] - s0;   // multiple of 8

    float acc = 0.0f;
    for (int base = 0; base < cntp; base += 32) {
        int idx = base + lane;
        unsigned long long pk = 0;
        if (idx < cntp) pk = g_epack[s0 + idx];
        int rem = cntp - base;      // multiple of 8, > 0
        #pragma unroll
        for (int jj = 0; jj < 32; jj += 8) {
            if (jj >= rem) break;   // warp-uniform
            #pragma unroll
            for (int j = jj; j < jj + 8; j++) {
                unsigned long long v = __shfl_sync(0xffffffffu, pk, j);
                int   s  = (int)(v & 0xffffffffu);
                float wt = __uint_as_float((unsigned)(v >> 32));
                if (active) acc += wt * __ldg(g_z + s * ZP + lane);
            }
        }
    }

    float val = active ? (acc + g_r[(long)n * F + lane]) : 0.0f;
    float ss = val * val;
    #pragma unroll
    for (int o = 16; o > 0; o >>= 1) ss += __shfl_xor_sync(0xffffffffu, ss, o);
    float inv = 1.0f / fmaxf(sqrtf(ss), 1e-12f);
    if (active) g_h[(long)n * F + lane] = fmaxf(val * inv, 0.0f);
}

// ---------------- pooling + final linear (batch sorted -> no atomics) --------
__device__ __forceinline__ int lower_bound_i(const int* __restrict__ a, int n, int key) {
    int lo = 0, hi = n;
    while (lo < hi) {
        int m = (lo + hi) >> 1;
        if (a[m] < key) lo = m + 1; else hi = m;
    }
    return lo;
}

__global__ void __launch_bounds__(256) pool_kernel(const int* __restrict__ batch,
                                                   const float* __restrict__ Wlin,
                                                   const float* __restrict__ blin,
                                                   float* __restrict__ out) {
    const float* emb = g_h;
    int g = blockIdx.x;

    __shared__ int s_lo, s_hi;
    if (threadIdx.x == 0) {
        s_lo = lower_bound_i(batch, NN, g);
        s_hi = lower_bound_i(batch, NN, g + 1);
    }
    __syncthreads();
    int lo = s_lo, hi = s_hi;

    float sm[F], mx[F];
    #pragma unroll
    for (int k = 0; k < F; k++) { sm[k] = 0.0f; mx[k] = 0.0f; }

    for (int i = lo + threadIdx.x; i < hi; i += blockDim.x) {
        const float* r = emb + (long)i * F;
        #pragma unroll
        for (int k = 0; k < F; k++) {
            float v = __ldg(r + k);
            sm[k] += v;
            mx[k] = fmaxf(mx[k], v);
        }
    }

    #pragma unroll
    for (int o = 16; o > 0; o >>= 1) {
        #pragma unroll
        for (int k = 0; k < F; k++) {
            sm[k] += __shfl_down_sync(0xffffffffu, sm[k], o);
            mx[k] = fmaxf(mx[k], __shfl_down_sync(0xffffffffu, mx[k], o));
        }
    }

    __shared__ float ssum[8][F];
    __shared__ float smax[8][F];
    int w = threadIdx.x >> 5, lane = threadIdx.x & 31;
    if (lane == 0) {
        #pragma unroll
        for (int k = 0; k < F; k++) { ssum[w][k] = sm[k]; smax[w][k] = mx[k]; }
    }
    __syncthreads();

    if (threadIdx.x == 0) {
        float fs[F], fm[F];
        #pragma unroll
        for (int k = 0; k < F; k++) { fs[k] = 0.0f; fm[k] = 0.0f; }
        for (int ww = 0; ww < 8; ww++)
            for (int k = 0; k < F; k++) {
                fs[k] += ssum[ww][k];
                fm[k] = fmaxf(fm[k], smax[ww][k]);
            }
        float cnt  = (float)(hi - lo);
        float invc = 1.0f / fmaxf(cnt, 1.0f);
        #pragma unroll
        for (int c = 0; c < 2; c++) {
            float v = blin[c];
            for (int k = 0; k < F; k++) v += fm[k] * Wlin[c * 40 + k];
            for (int k = 0; k < F; k++) v += fs[k] * invc * Wlin[c * 40 + 20 + k];
            out[g * 2 + c] = v;
        }
    }
}

// ---------------- launch ------------------------------------------------------
extern "C" void kernel_launch(void* const* d_in, const int* in_sizes, int n_in,
                              void* d_out, int out_size) {
    (void)in_sizes; (void)n_in; (void)out_size;

    const float* x      = (const float*)d_in[0];
    const int*   ei     = (const int*)  d_in[1];   // [2, NE]: row0=src, row1=dst
    const int*   batch  = (const int*)  d_in[2];
    const float* ew     = (const float*)d_in[3];
    const float* W1_rel = (const float*)d_in[4];
    const float* b1_rel = (const float*)d_in[5];
    const float* W1_root= (const float*)d_in[6];
    const float* W2_rel = (const float*)d_in[7];
    const float* b2_rel = (const float*)d_in[8];
    const float* W2_root= (const float*)d_in[9];
    const float* W3_rel = (const float*)d_in[10];
    const float* b3_rel = (const float*)d_in[11];
    const float* W3_root= (const float*)d_in[12];
    const float* W_lin  = (const float*)d_in[13];
    const float* b_lin  = (const float*)d_in[14];
    float* out = (float*)d_out;

    const int* src = ei;
    const int* dst = ei + NE;

    const int TB = 256;
    const int GB_N  = (NN + TB - 1) / TB;           // 391
    const int GB_E4 = (NE / 4 + TB - 1) / TB;       // 3125
    const int GB_W  = (NN * 32 + TB - 1) / TB;      // 12500

    hist_kernel   <<<GB_E4, TB>>>(dst);             // 0
    scan1_kernel  <<<SCAN_BLOCKS, TB>>>();          // 1
    scan3_kernel  <<<SCAN_BLOCKS, TB>>>();          // 2
    scatter_kernel<<<GB_E4, TB>>>(src, dst, ew);    // 3

    transform_kernel<10><<<GB_N, TB>>>(x, W1_rel, b1_rel, W1_root, -1);  // 4
    gather_kernel<<<GB_W, TB>>>();                                        // 5  <- ncu -s 5
    transform_kernel<20><<<GB_N, TB>>>(x, W2_rel, b2_rel, W2_root, 0);
    gather_kernel<<<GB_W, TB>>>();
    transform_kernel<20><<<GB_N, TB>>>(x, W3_rel, b3_rel, W3_root, 0);
    gather_kernel<<<GB_W, TB>>>();

    pool_kernel<<<NG, 256>>>(batch, W_lin, b_lin, out);
}